// round 8
// baseline (speedup 1.0000x reference)
#include <cuda_runtime.h>
#include <cuda_bf16.h>
#include <math.h>

// Problem constants: B=32, N=128, D=256, H=8, DK=32
typedef unsigned int u32;
typedef __nv_bfloat16 bf16;

// ---------------- scratch (static device globals; no allocation) -------------
__device__ __align__(16) float g_fA[1024 * 256];
__device__ __align__(16) float g_fB[1024 * 256];
__device__ __align__(16) float g_conn[8 * 128 * 128];
__device__ __align__(16) float g_cb[3 * 256];            // composed QKV biases
__device__ __align__(16) bf16 g_wphi[8 * 65536];         // fcA,fcB,w1,ow,w2,wq,wk,wv
__device__ __align__(16) bf16 g_wplo[8 * 65536];
__device__ __align__(16) bf16 g_cwhi[3 * 65536];         // composed W2@Wq/k/v
__device__ __align__(16) bf16 g_cwlo[3 * 65536];
__device__ __align__(16) bf16 g_fthi[1024 * 256];        // feats planes
__device__ __align__(16) bf16 g_ftlo[1024 * 256];
__device__ __align__(16) bf16 g_xhi[4096 * 256];         // x planes
__device__ __align__(16) bf16 g_xlo[4096 * 256];
__device__ __align__(16) bf16 g_h1hi[4096 * 256];
__device__ __align__(16) bf16 g_h1lo[4096 * 256];
__device__ __align__(16) bf16 g_aohi[4096 * 256];
__device__ __align__(16) bf16 g_aolo[4096 * 256];

__device__ __forceinline__ float gelu_tanh(float x) {
    float x3 = x * x * x;
    float t = tanhf(0.7978845608028654f * (x + 0.044715f * x3));
    return 0.5f * x * (1.0f + t);
}

__device__ __forceinline__ void split_bf16(float v, bf16& h, bf16& l) {
    h = __float2bfloat16_rn(v);
    l = __float2bfloat16_rn(v - __bfloat162float(h));
}

__device__ __forceinline__ void cvt4(float4 v, uint2& hi, uint2& lo) {
    bf16 h0, l0, h1, l1, h2, l2, h3, l3;
    split_bf16(v.x, h0, l0); split_bf16(v.y, h1, l1);
    split_bf16(v.z, h2, l2); split_bf16(v.w, h3, l3);
    __nv_bfloat162 a, b, c, d;
    a.x = h0; a.y = h1; b.x = h2; b.y = h3;
    c.x = l0; c.y = l1; d.x = l2; d.y = l3;
    hi.x = *(u32*)&a; hi.y = *(u32*)&b;
    lo.x = *(u32*)&c; lo.y = *(u32*)&d;
}

__device__ __forceinline__ void packP(float x, float y, u32& hi, u32& lo) {
    bf16 hx, lx, hy, ly;
    split_bf16(x, hx, lx);
    split_bf16(y, hy, ly);
    __nv_bfloat162 H; H.x = hx; H.y = hy;
    __nv_bfloat162 L; L.x = lx; L.y = ly;
    hi = *(u32*)&H; lo = *(u32*)&L;
}

#define LDSM4(r, addr)                                                        \
    asm volatile("ldmatrix.sync.aligned.m8n8.x4.shared.b16 {%0,%1,%2,%3}, [%4];" \
                 : "=r"(r[0]), "=r"(r[1]), "=r"(r[2]), "=r"(r[3]) : "r"(addr))

#define LDSM4T(r, addr)                                                       \
    asm volatile("ldmatrix.sync.aligned.m8n8.x4.trans.shared.b16 {%0,%1,%2,%3}, [%4];" \
                 : "=r"(r[0]), "=r"(r[1]), "=r"(r[2]), "=r"(r[3]) : "r"(addr))

#define MMA16816(d, a, b)                                                     \
    asm volatile("mma.sync.aligned.m16n8k16.row.col.f32.bf16.bf16.f32 "       \
                 "{%0,%1,%2,%3}, {%4,%5,%6,%7}, {%8,%9}, {%0,%1,%2,%3};"      \
                 : "+f"(d[0]), "+f"(d[1]), "+f"(d[2]), "+f"(d[3])             \
                 : "r"(a[0]), "r"(a[1]), "r"(a[2]), "r"(a[3]),                \
                   "r"(b[0]), "r"(b[1]))

// ---------------- L0: convert weights / feats / x to bf16 hi/lo planes -------
struct CvtParams {
    const float* src[8];
    const float* mw;
    const float* x;
};

__global__ void __launch_bounds__(256)
k_cvt(CvtParams P)
{
    int bid = blockIdx.x, t = threadIdx.x;
    const float* s;
    bf16 *hi, *lo;
    int base;
    if (bid < 256) {
        int task = bid >> 5;
        base = (bid & 31) * 2048 + t * 8;
        s = P.src[task] + base;
        hi = g_wphi + task * 65536 + base;
        lo = g_wplo + task * 65536 + base;
    } else if (bid < 384) {
        int e = (bid - 256) * 2048 + t * 8;
        int row = e >> 8, d = e & 255;
        int h = row >> 7, n = row & 127;
        s = P.mw + n * 2048 + h * 256 + d;
        hi = g_fthi + e; lo = g_ftlo + e;
    } else {
        int e = (bid - 384) * 2048 + t * 8;
        s = P.x + e;
        hi = g_xhi + e; lo = g_xlo + e;
    }
    float4 a = *(const float4*)s;
    float4 b = *(const float4*)(s + 4);
    uint2 h0, l0, h1, l1;
    cvt4(a, h0, l0); cvt4(b, h1, l1);
    *(uint2*)hi = h0; *(uint2*)(hi + 4) = h1;
    *(uint2*)lo = l0; *(uint2*)(lo + 4) = l1;
}

// ---------------- GEMM-32: BM=32, BN=64, BK=32, plane A and plane W ----------
struct Job {
    const bf16 *Ahi, *Alo;
    const bf16 *Whi, *Wlo;
    const float* bias;
    float* Cf;
    bf16 *Chi, *Clo;
    int act;
    int storeMode;  // 0 fp32, 1 bf16 planes
};

struct ConnArgs {
    const float *fcb, *fccw, *fccb, *gu;
    const float *b2, *wq, *wk, *wv, *bq, *bk, *bv;
};

__device__ void connJob(int cid, ConnArgs CA, char* smemRaw);

__device__ void biasJob(int z, ConnArgs CA) {
    int c = threadIdx.x;
    const float* wz = (z == 0) ? CA.wq : (z == 1) ? CA.wk : CA.wv;
    const float* bz = (z == 0) ? CA.bq : (z == 1) ? CA.bk : CA.bv;
    float acc = bz[c];
    for (int d = 0; d < 256; d++)
        acc = fmaf(CA.b2[d], wz[d * 256 + c], acc);
    g_cb[z * 256 + c] = acc;
}

__global__ void __launch_bounds__(256)
k_gemm32(Job j0, Job j1, Job j2, int n0, int n01, int n012, ConnArgs CA)
{
    __shared__ __align__(16) char smemRaw[28672];

    int jid = blockIdx.x;
    if (jid >= n012 + 128) { biasJob(jid - n012 - 128, CA); return; }
    if (jid >= n012)       { connJob(jid - n012, CA, smemRaw); return; }

    Job J; int tile;
    if (jid < n0)       { J = j0; tile = jid; }
    else if (jid < n01) { J = j1; tile = jid - n0; }
    else                { J = j2; tile = jid - n01; }

    bf16* sAhi = (bf16*)smemRaw;            // [2][32*40]
    bf16* sAlo = sAhi + 2 * 1280;
    bf16* sWhi = sAlo + 2 * 1280;           // [2][32*72]
    bf16* sWlo = sWhi + 2 * 2304;

    int rowBase = (tile >> 2) * 32;
    int colBase = (tile & 3) * 64;

    int t = threadIdx.x;
    int warp = t >> 5, lane = t & 31;
    int wm = warp >> 2, wn = warp & 3;
    int g = lane >> 3, r = lane & 7;

    u32 sAhiB = (u32)__cvta_generic_to_shared(sAhi);
    u32 sAloB = (u32)__cvta_generic_to_shared(sAlo);
    u32 sWhiB = (u32)__cvta_generic_to_shared(sWhi);
    u32 sWloB = (u32)__cvta_generic_to_shared(sWlo);

    int pl = t >> 7, ps = t & 127;
    int prow = ps >> 2, pseg = ps & 3;   // A: 32 rows x 4 uint4
    int wr = ps >> 3, wsg = ps & 7;      // W: entries ps, ps+128 -> rows wr, wr+16

    uint4 pa, pw0, pw1;

    auto loadTile = [&](int kt) {
        const bf16* asrc = pl ? J.Alo : J.Ahi;
        pa = *(const uint4*)&asrc[(rowBase + prow) * 256 + kt + pseg * 8];
        const bf16* wsrc = pl ? J.Wlo : J.Whi;
        pw0 = *(const uint4*)&wsrc[(kt + wr) * 256 + colBase + wsg * 8];
        pw1 = *(const uint4*)&wsrc[(kt + wr + 16) * 256 + colBase + wsg * 8];
    };

    auto storeTile = [&](int bb) {
        bf16* ad = pl ? sAlo : sAhi;
        *(uint4*)&ad[bb * 1280 + prow * 40 + pseg * 8] = pa;
        bf16* wd = pl ? sWlo : sWhi;
        *(uint4*)&wd[bb * 2304 + wr * 72 + wsg * 8] = pw0;
        *(uint4*)&wd[bb * 2304 + (wr + 16) * 72 + wsg * 8] = pw1;
    };

    float acc[2][4];
    #pragma unroll
    for (int nt = 0; nt < 2; nt++)
        #pragma unroll
        for (int i = 0; i < 4; i++) acc[nt][i] = 0.0f;

    loadTile(0);
    storeTile(0);
    __syncthreads();

    #pragma unroll
    for (int it = 0; it < 8; it++) {
        int bb = it & 1;
        if (it < 7) loadTile((it + 1) * 32);

        #pragma unroll
        for (int ks = 0; ks < 32; ks += 16) {
            u32 ah[4], al[4], bh[4], bl[4];
            {
                int rowA = wm * 16 + r + ((g & 1) << 3);
                int kcol = ks + ((g >> 1) << 3);
                u32 off = (u32)(bb * 1280 + rowA * 40 + kcol) * 2;
                LDSM4(ah, sAhiB + off);
                LDSM4(al, sAloB + off);
            }
            {
                int krow = ks + r + ((g & 1) << 3);
                int ncol = wn * 16 + ((g >> 1) << 3);
                u32 off = (u32)(bb * 2304 + krow * 72 + ncol) * 2;
                LDSM4T(bh, sWhiB + off);
                LDSM4T(bl, sWloB + off);
            }
            #pragma unroll
            for (int nt = 0; nt < 2; nt++) {
                MMA16816(acc[nt], ah, (&bh[nt * 2]));
                MMA16816(acc[nt], ah, (&bl[nt * 2]));
                MMA16816(acc[nt], al, (&bh[nt * 2]));
            }
        }
        __syncthreads();
        if (it < 7) {
            storeTile(1 - bb);
            __syncthreads();
        }
    }

    #pragma unroll
    for (int nt = 0; nt < 2; nt++) {
        int row0 = rowBase + wm * 16 + (lane >> 2);
        int col0 = colBase + wn * 16 + nt * 8 + (lane & 3) * 2;
        float bv0 = J.bias ? J.bias[col0] : 0.0f;
        float bv1 = J.bias ? J.bias[col0 + 1] : 0.0f;
        #pragma unroll
        for (int half = 0; half < 2; half++) {
            int row = row0 + half * 8;
            float v0 = acc[nt][half * 2 + 0] + bv0;
            float v1 = acc[nt][half * 2 + 1] + bv1;
            if (J.act) { v0 = gelu_tanh(v0); v1 = gelu_tanh(v1); }
            if (J.storeMode == 0) {
                *(float2*)&J.Cf[row * 256 + col0] = make_float2(v0, v1);
            } else {
                u32 hi, lo;
                packP(v0, v1, hi, lo);
                *(u32*)&J.Chi[row * 256 + col0] = hi;
                *(u32*)&J.Clo[row * 256 + col0] = lo;
            }
        }
    }
}

// ---------------- conn job: 32i x 32j, 256 threads ---------------------------
__device__ void connJob(int cid, ConnArgs CA, char* smemRaw)
{
    float (*Aj)[33] = (float(*)[33])smemRaw;
    float (*Bi)[33] = (float(*)[33])(smemRaw + 32 * 33 * 4);
    float* Cs0 = (float*)(smemRaw + 2 * 32 * 33 * 4);
    float* Cs1 = Cs0 + 256;

    int h = cid >> 4;
    int ibase = ((cid >> 2) & 3) * 32;
    int jbase = (cid & 3) * 32;
    int t = threadIdx.x;
    int tx = t & 15, ty = t >> 4;

    Cs0[t] = CA.fccw[2 * t];
    Cs1[t] = CA.fccw[2 * t + 1];

    float l0[2][2] = {{0.f, 0.f}, {0.f, 0.f}};
    float l1[2][2] = {{0.f, 0.f}, {0.f, 0.f}};

    for (int d0 = 0; d0 < 256; d0 += 32) {
        if (d0) __syncthreads();
        int jr = t >> 3, c = (t & 7) * 4;
        float4 va = *(const float4*)&g_fA[(h * 128 + jbase + jr) * 256 + d0 + c];
        Aj[jr][c] = va.x; Aj[jr][c + 1] = va.y; Aj[jr][c + 2] = va.z; Aj[jr][c + 3] = va.w;
        float4 vb = *(const float4*)&g_fB[(h * 128 + ibase + jr) * 256 + d0 + c];
        float4 o = *(const float4*)&CA.fcb[d0 + c];
        Bi[jr][c] = vb.x + o.x; Bi[jr][c + 1] = vb.y + o.y;
        Bi[jr][c + 2] = vb.z + o.z; Bi[jr][c + 3] = vb.w + o.w;
        __syncthreads();

        #pragma unroll
        for (int dd = 0; dd < 32; dd++) {
            float a0 = Aj[tx * 2][dd], a1 = Aj[tx * 2 + 1][dd];
            float b0 = Bi[ty * 2][dd], b1 = Bi[ty * 2 + 1][dd];
            float c0v = Cs0[d0 + dd], c1v = Cs1[d0 + dd];
            float r00 = fmaxf(a0 + b0, 0.f), r10 = fmaxf(a1 + b0, 0.f);
            float r01 = fmaxf(a0 + b1, 0.f), r11 = fmaxf(a1 + b1, 0.f);
            l0[0][0] = fmaf(r00, c0v, l0[0][0]); l1[0][0] = fmaf(r00, c1v, l1[0][0]);
            l0[0][1] = fmaf(r10, c0v, l0[0][1]); l1[0][1] = fmaf(r10, c1v, l1[0][1]);
            l0[1][0] = fmaf(r01, c0v, l0[1][0]); l1[1][0] = fmaf(r01, c1v, l1[1][0]);
            l0[1][1] = fmaf(r11, c0v, l0[1][1]); l1[1][1] = fmaf(r11, c1v, l1[1][1]);
        }
    }

    float cb0 = CA.fccb[0], cb1 = CA.fccb[1];
    #pragma unroll
    for (int ii = 0; ii < 2; ii++) {
        int i = ibase + ty * 2 + ii;
        #pragma unroll
        for (int jj = 0; jj < 2; jj++) {
            int j = jbase + tx * 2 + jj;
            int idx = (h * 128 + i) * 128 + j;
            float2 u2 = *(const float2*)&CA.gu[idx * 2];
            float gg0 = -logf(-logf(u2.x + 1e-10f) + 1e-10f);
            float gg1 = -logf(-logf(u2.y + 1e-10f) + 1e-10f);
            g_conn[idx] = ((l1[ii][jj] + cb1 + gg1) > (l0[ii][jj] + cb0 + gg0)) ? 1.0f : 0.0f;
        }
    }
}

// ---------------- fused QKV + tensor-core attention: one CTA per (b,h) -------
// Q/K/V = h1 @ composedW heads + composed bias; attention as in R7.
#define QKV_SMEM (67584 + 2048)

__global__ void __launch_bounds__(256)
k_qkv_attn()
{
    extern __shared__ char sm[];
    bf16* sAhi = (bf16*)sm;                  // [2][128*40]
    bf16* sAlo = sAhi + 2 * 5120;
    bf16* sWhi = sAlo + 2 * 5120;            // [2][32*104]
    bf16* sWlo = sWhi + 2 * 3328;
    bf16* sQhi = (bf16*)sm;                  // overlay post-GEMM
    bf16* sQlo = sQhi + 5120;
    bf16* sKhi = sQlo + 5120;
    bf16* sKlo = sKhi + 5120;
    bf16* sVhi = sKlo + 5120;
    bf16* sVlo = sVhi + 5120;
    u32* cmask = (u32*)(sm + 67584);

    int bid = blockIdx.x;
    int b = bid >> 3, h = bid & 7;
    int t = threadIdx.x;
    int warp = t >> 5, lane = t & 31;
    int g = lane >> 3, r = lane & 7;
    int gRow = b * 128;

    u32 smB = (u32)__cvta_generic_to_shared(sm);
    u32 sAhiB = smB, sAloB = smB + 20480, sWhiB = smB + 40960, sWloB = smB + 54272;
    u32 sQhiB = smB, sQloB = smB + 10240;
    u32 sKhiB = smB + 20480, sKloB = smB + 30720;
    u32 sVhiB = smB + 40960, sVloB = smB + 51200;

    // conn bitmask
    {
        const float* cr = g_conn + h * 16384;
        for (int i0b = 0; i0b < 128; i0b += 2) {
            int i0 = i0b + (warp >> 2);
            float c = cr[i0 * 128 + (warp & 3) * 32 + lane];
            u32 bal = __ballot_sync(0xffffffffu, c > 0.5f);
            if (lane == 0) cmask[i0 * 4 + (warp & 3)] = bal;
        }
    }

    // ---- Phase 1: QKV GEMM 128x96, k=256, A = h1 planes, W = composed planes
    int wpl = t >> 7, wi = t & 127;
    int wr = wi >> 2, ws = wi & 3;
    uint4 pah[2], pal[2], pw[3];

    auto loadTile = [&](int kt) {
        #pragma unroll
        for (int u = 0; u < 2; u++) {
            int s = t * 2 + u;
            int row = s >> 2, seg = s & 3;
            pah[u] = *(const uint4*)&g_h1hi[(gRow + row) * 256 + kt + seg * 8];
            pal[u] = *(const uint4*)&g_h1lo[(gRow + row) * 256 + kt + seg * 8];
        }
        const bf16* wb = wpl ? g_cwlo : g_cwhi;
        #pragma unroll
        for (int z = 0; z < 3; z++)
            pw[z] = *(const uint4*)&wb[z * 65536 + (kt + wr) * 256 + h * 32 + ws * 8];
    };

    auto storeTile = [&](int bb) {
        #pragma unroll
        for (int u = 0; u < 2; u++) {
            int s = t * 2 + u;
            int row = s >> 2, seg = s & 3;
            *(uint4*)&sAhi[bb * 5120 + row * 40 + seg * 8] = pah[u];
            *(uint4*)&sAlo[bb * 5120 + row * 40 + seg * 8] = pal[u];
        }
        bf16* wd = wpl ? sWlo : sWhi;
        #pragma unroll
        for (int z = 0; z < 3; z++)
            *(uint4*)&wd[bb * 3328 + wr * 104 + z * 32 + ws * 8] = pw[z];
    };

    float acc[12][4];
    #pragma unroll
    for (int j = 0; j < 12; j++)
        #pragma unroll
        for (int i = 0; i < 4; i++) acc[j][i] = 0.0f;

    loadTile(0);
    storeTile(0);
    __syncthreads();

    #pragma unroll
    for (int it = 0; it < 8; it++) {
        int bb = it & 1;
        if (it < 7) loadTile((it + 1) * 32);

        #pragma unroll
        for (int ks = 0; ks < 32; ks += 16) {
            u32 ah[4], al[4];
            {
                int rowA = warp * 16 + r + ((g & 1) << 3);
                int kcol = ks + ((g >> 1) << 3);
                u32 off = (u32)(bb * 5120 + rowA * 40 + kcol) * 2;
                LDSM4(ah, sAhiB + off);
                LDSM4(al, sAloB + off);
            }
            #pragma unroll
            for (int n16 = 0; n16 < 6; n16++) {
                u32 bh[4], bl[4];
                int krow = ks + r + ((g & 1) << 3);
                int ncol = n16 * 16 + ((g >> 1) << 3);
                u32 off = (u32)(bb * 3328 + krow * 104 + ncol) * 2;
                LDSM4T(bh, sWhiB + off);
                LDSM4T(bl, sWloB + off);
                MMA16816(acc[n16 * 2], ah, (&bh[0]));
                MMA16816(acc[n16 * 2], ah, (&bl[0]));
                MMA16816(acc[n16 * 2], al, (&bh[0]));
                MMA16816(acc[n16 * 2 + 1], ah, (&bh[2]));
                MMA16816(acc[n16 * 2 + 1], ah, (&bl[2]));
                MMA16816(acc[n16 * 2 + 1], al, (&bh[2]));
            }
        }
        __syncthreads();
        if (it < 7) {
            storeTile(1 - bb);
            __syncthreads();
        }
    }

    // epilogue: composed bias + scale, write plane overlay
    const float scale = 0.17677669529663687f;  // 1/sqrt(32)
    #pragma unroll
    for (int j = 0; j < 12; j++) {
        int colg = j * 8 + (lane & 3) * 2;
        int z = colg >> 5, c = colg & 31;
        bf16* zhi = (z == 0) ? sQhi : (z == 1) ? sKhi : sVhi;
        bf16* zlo = (z == 0) ? sQlo : (z == 1) ? sKlo : sVlo;
        float scl = (z == 0) ? scale : 1.0f;
        float b0 = g_cb[z * 256 + h * 32 + c];
        float b1 = g_cb[z * 256 + h * 32 + c + 1];
        #pragma unroll
        for (int half = 0; half < 2; half++) {
            int row = warp * 16 + (lane >> 2) + half * 8;
            float v0 = (acc[j][half * 2] + b0) * scl;
            float v1 = (acc[j][half * 2 + 1] + b1) * scl;
            u32 hi, lo;
            packP(v0, v1, hi, lo);
            *(u32*)&zhi[row * 40 + c] = hi;
            *(u32*)&zlo[row * 40 + c] = lo;
        }
    }
    __syncthreads();

    // ---- Phase 2: tensor-core attention ----
    u32 aQh[2][4], aQl[2][4];
    #pragma unroll
    for (int kt = 0; kt < 2; kt++) {
        int rowA = warp * 16 + r + ((g & 1) << 3);
        int kcol = kt * 16 + ((g >> 1) << 3);
        u32 off = (u32)(rowA * 40 + kcol) * 2;
        LDSM4(aQh[kt], sQhiB + off);
        LDSM4(aQl[kt], sQloB + off);
    }

    float accS[16][4];
    #pragma unroll
    for (int nt = 0; nt < 16; nt++)
        #pragma unroll
        for (int i = 0; i < 4; i++) accS[nt][i] = 0.0f;

    #pragma unroll
    for (int kt = 0; kt < 2; kt++) {
        #pragma unroll
        for (int ng = 0; ng < 8; ng++) {
            u32 kbh[4], kbl[4];
            int nrow = ng * 16 + r + ((g & 1) << 3);
            int kcol = kt * 16 + ((g >> 1) << 3);
            u32 off = (u32)(nrow * 40 + kcol) * 2;
            LDSM4(kbh, sKhiB + off);
            LDSM4(kbl, sKloB + off);
            u32 b0h[2] = {kbh[0], kbh[2]}, b1h[2] = {kbh[1], kbh[3]};
            u32 b0l[2] = {kbl[0], kbl[2]}, b1l[2] = {kbl[1], kbl[3]};
            MMA16816(accS[ng * 2], aQh[kt], b0h);
            MMA16816(accS[ng * 2], aQh[kt], b0l);
            MMA16816(accS[ng * 2], aQl[kt], b0h);
            MMA16816(accS[ng * 2 + 1], aQh[kt], b1h);
            MMA16816(accS[ng * 2 + 1], aQh[kt], b1l);
            MMA16816(accS[ng * 2 + 1], aQl[kt], b1h);
        }
    }

    int rA = warp * 16 + (lane >> 2);
    int rB = rA + 8;
    u32 mA[4], mB[4];
    #pragma unroll
    for (int w2 = 0; w2 < 4; w2++) { mA[w2] = cmask[rA * 4 + w2]; mB[w2] = cmask[rB * 4 + w2]; }
    #pragma unroll
    for (int nt = 0; nt < 16; nt++) {
        int c0 = nt * 8 + (lane & 3) * 2;
        int w2 = c0 >> 5, bit = c0 & 31;
        if (!((mA[w2] >> bit) & 1u))       accS[nt][0] = -INFINITY;
        if (!((mA[w2] >> (bit + 1)) & 1u)) accS[nt][1] = -INFINITY;
        if (!((mB[w2] >> bit) & 1u))       accS[nt][2] = -INFINITY;
        if (!((mB[w2] >> (bit + 1)) & 1u)) accS[nt][3] = -INFINITY;
    }

    float mxA = -INFINITY, mxB = -INFINITY;
    #pragma unroll
    for (int nt = 0; nt < 16; nt++) {
        mxA = fmaxf(mxA, fmaxf(accS[nt][0], accS[nt][1]));
        mxB = fmaxf(mxB, fmaxf(accS[nt][2], accS[nt][3]));
    }
    mxA = fmaxf(mxA, __shfl_xor_sync(0xffffffffu, mxA, 1));
    mxA = fmaxf(mxA, __shfl_xor_sync(0xffffffffu, mxA, 2));
    mxB = fmaxf(mxB, __shfl_xor_sync(0xffffffffu, mxB, 1));
    mxB = fmaxf(mxB, __shfl_xor_sync(0xffffffffu, mxB, 2));

    float sA = 0.0f, sB = 0.0f;
    #pragma unroll
    for (int nt = 0; nt < 16; nt++) {
        accS[nt][0] = expf(accS[nt][0] - mxA);
        accS[nt][1] = expf(accS[nt][1] - mxA);
        accS[nt][2] = expf(accS[nt][2] - mxB);
        accS[nt][3] = expf(accS[nt][3] - mxB);
        sA += accS[nt][0] + accS[nt][1];
        sB += accS[nt][2] + accS[nt][3];
    }
    sA += __shfl_xor_sync(0xffffffffu, sA, 1);
    sA += __shfl_xor_sync(0xffffffffu, sA, 2);
    sB += __shfl_xor_sync(0xffffffffu, sB, 1);
    sB += __shfl_xor_sync(0xffffffffu, sB, 2);
    float invA = 1.0f / sA, invB = 1.0f / sB;

    float accO[4][4];
    #pragma unroll
    for (int nt = 0; nt < 4; nt++)
        #pragma unroll
        for (int i = 0; i < 4; i++) accO[nt][i] = 0.0f;

    #pragma unroll
    for (int kt = 0; kt < 8; kt++) {
        u32 ph[4], plo[4];
        packP(accS[2 * kt][0],     accS[2 * kt][1],     ph[0], plo[0]);
        packP(accS[2 * kt][2],     accS[2 * kt][3],     ph[1], plo[1]);
        packP(accS[2 * kt + 1][0], accS[2 * kt + 1][1], ph[2], plo[2]);
        packP(accS[2 * kt + 1][2], accS[2 * kt + 1][3], ph[3], plo[3]);
        #pragma unroll
        for (int n16 = 0; n16 < 2; n16++) {
            u32 vbh[4], vbl[4];
            int krow = kt * 16 + r + ((g & 1) << 3);
            int ncol = n16 * 16 + ((g >> 1) << 3);
            u32 off = (u32)(krow * 40 + ncol) * 2;
            LDSM4T(vbh, sVhiB + off);
            LDSM4T(vbl, sVloB + off);
            MMA16816(accO[n16 * 2], ph, (&vbh[0]));
            MMA16816(accO[n16 * 2], ph, (&vbl[0]));
            MMA16816(accO[n16 * 2], plo, (&vbh[0]));
            MMA16816(accO[n16 * 2 + 1], ph, (&vbh[2]));
            MMA16816(accO[n16 * 2 + 1], ph, (&vbl[2]));
            MMA16816(accO[n16 * 2 + 1], plo, (&vbh[2]));
        }
    }

    #pragma unroll
    for (int nt = 0; nt < 4; nt++) {
        int c0 = nt * 8 + (lane & 3) * 2;
        int oA = (b * 128 + rA) * 256 + h * 32 + c0;
        int oB = (b * 128 + rB) * 256 + h * 32 + c0;
        u32 hi, lo;
        packP(accO[nt][0] * invA, accO[nt][1] * invA, hi, lo);
        *(u32*)&g_aohi[oA] = hi; *(u32*)&g_aolo[oA] = lo;
        packP(accO[nt][2] * invB, accO[nt][3] * invB, hi, lo);
        *(u32*)&g_aohi[oB] = hi; *(u32*)&g_aolo[oB] = lo;
    }
}

// ---------------- launch ------------------------------------------------------
extern "C" void kernel_launch(void* const* d_in, const int* in_sizes, int n_in,
                              void* d_out, int out_size)
{
    const float* x        = (const float*)d_in[0];
    const float* gumbel_u = (const float*)d_in[1];
    const float* memory_w = (const float*)d_in[2];
    const float* fc_out_w = (const float*)d_in[3];
    const float* fc_out_b = (const float*)d_in[4];
    const float* fc_cat_w = (const float*)d_in[5];
    const float* fc_cat_b = (const float*)d_in[6];
    const float* wq       = (const float*)d_in[7];
    const float* bq       = (const float*)d_in[8];
    const float* wk       = (const float*)d_in[9];
    const float* bk       = (const float*)d_in[10];
    const float* wv       = (const float*)d_in[11];
    const float* bv       = (const float*)d_in[12];
    const float* out_w    = (const float*)d_in[13];
    const float* out_b    = (const float*)d_in[14];
    const float* mlp_w1   = (const float*)d_in[15];
    const float* mlp_b1   = (const float*)d_in[16];
    const float* mlp_w2   = (const float*)d_in[17];
    const float* mlp_b2   = (const float*)d_in[18];

    float *fA, *fB;
    cudaGetSymbolAddress((void**)&fA, g_fA);
    cudaGetSymbolAddress((void**)&fB, g_fB);
    bf16 *wphi, *wplo, *fthi, *ftlo, *xhi, *xlo, *cwhi, *cwlo, *h1hi, *h1lo, *aohi, *aolo;
    cudaGetSymbolAddress((void**)&wphi, g_wphi);
    cudaGetSymbolAddress((void**)&wplo, g_wplo);
    cudaGetSymbolAddress((void**)&fthi, g_fthi);
    cudaGetSymbolAddress((void**)&ftlo, g_ftlo);
    cudaGetSymbolAddress((void**)&xhi, g_xhi);
    cudaGetSymbolAddress((void**)&xlo, g_xlo);
    cudaGetSymbolAddress((void**)&cwhi, g_cwhi);
    cudaGetSymbolAddress((void**)&cwlo, g_cwlo);
    cudaGetSymbolAddress((void**)&h1hi, g_h1hi);
    cudaGetSymbolAddress((void**)&h1lo, g_h1lo);
    cudaGetSymbolAddress((void**)&aohi, g_aohi);
    cudaGetSymbolAddress((void**)&aolo, g_aolo);

    static bool attrSet = false;
    if (!attrSet) {
        cudaFuncSetAttribute(k_qkv_attn, cudaFuncAttributeMaxDynamicSharedMemorySize, QKV_SMEM);
        attrSet = true;
    }

    ConnArgs CA = { fc_out_b, fc_cat_w, fc_cat_b, gumbel_u,
                    mlp_b2, wq, wk, wv, bq, bk, bv };
    Job JZ = {};

    // L0: convert weights / feats / x to planes  (896 blocks)
    {
        CvtParams CP;
        CP.src[0] = fc_out_w;          CP.src[1] = fc_out_w + 65536;
        CP.src[2] = mlp_w1;            CP.src[3] = out_w;
        CP.src[4] = mlp_w2;            CP.src[5] = wq;
        CP.src[6] = wk;                CP.src[7] = wv;
        CP.mw = memory_w;              CP.x = x;
        k_cvt<<<896, 256>>>(CP);
    }

    // L1: fA (128) + fB (128) + mlp1 (512) = 768 blocks
    {
        Job ja = JZ, jb = JZ, jm = JZ;
        ja.Ahi = fthi; ja.Alo = ftlo; ja.Whi = wphi;           ja.Wlo = wplo;           ja.Cf = fA;
        jb.Ahi = fthi; jb.Alo = ftlo; jb.Whi = wphi + 65536;   jb.Wlo = wplo + 65536;   jb.Cf = fB;
        jm.Ahi = xhi;  jm.Alo = xlo;
        jm.Whi = wphi + 2 * 65536; jm.Wlo = wplo + 2 * 65536;
        jm.bias = mlp_b1; jm.Chi = h1hi; jm.Clo = h1lo; jm.act = 1; jm.storeMode = 1;
        k_gemm32<<<768, 256>>>(ja, jb, jm, 128, 256, 768, CA);
    }

    // L2: compose W2@Wq/k/v (96) + conn (128) + bias compose (3) = 227 blocks
    {
        Job jq = JZ, jk = JZ, jv = JZ;
        jq.Ahi = wphi + 4 * 65536; jq.Alo = wplo + 4 * 65536;
        jq.Whi = wphi + 5 * 65536; jq.Wlo = wplo + 5 * 65536;
        jq.Chi = cwhi; jq.Clo = cwlo; jq.storeMode = 1;
        jk = jq; jk.Whi = wphi + 6 * 65536; jk.Wlo = wplo + 6 * 65536;
        jk.Chi = cwhi + 65536; jk.Clo = cwlo + 65536;
        jv = jq; jv.Whi = wphi + 7 * 65536; jv.Wlo = wplo + 7 * 65536;
        jv.Chi = cwhi + 2 * 65536; jv.Clo = cwlo + 2 * 65536;
        k_gemm32<<<227, 256>>>(jq, jk, jv, 32, 64, 96, CA);
    }

    // L3: fused QKV + tensor-core attention (256 CTAs)
    k_qkv_attn<<<256, 256, QKV_SMEM>>>();

    // L4: output projection -> d_out (512 blocks)
    {
        Job j = JZ;
        j.Ahi = aohi; j.Alo = aolo;
        j.Whi = wphi + 3 * 65536; j.Wlo = wplo + 3 * 65536;
        j.bias = out_b; j.Cf = (float*)d_out; j.storeMode = 0;
        k_gemm32<<<512, 256>>>(j, JZ, JZ, 512, 512, 512, CA);
    }
}